// round 14
// baseline (speedup 1.0000x reference)
#include <cuda_runtime.h>
#include <math.h>
#include <stdint.h>

#define T_LEN 1024
#define BATCH 32
#define DIN   256
#define HID   512
#define NB    128
#define NT    512

__device__ float g_xT[(long)T_LEN * BATCH * DIN];       // [t][b][d]  32MB
__device__ float g_hs4[(long)T_LEN * NB * BATCH * 4];   // [t][k4=blk][b][4j]
__device__ unsigned g_cnt16[1024];                      // 16 counters at w*64

// ---------------------------------------------------------------- helpers
__device__ __forceinline__ float fast_tanh(float x) {
  float y; asm("tanh.approx.f32 %0, %1;" : "=f"(y) : "f"(x)); return y;
}
__device__ __forceinline__ float fast_sig(float x) {
  return 0.5f * fast_tanh(0.5f * x) + 0.5f;
}
__device__ __forceinline__ void fma2(unsigned long long& d,
                                     unsigned long long a, unsigned long long b) {
  asm("fma.rn.f32x2 %0, %1, %2, %0;" : "+l"(d) : "l"(a), "l"(b));
}
__device__ __forceinline__ float hsum2(unsigned long long v) {
  return __uint_as_float((unsigned)v) + __uint_as_float((unsigned)(v >> 32));
}

// ---------------- phase 0: x[B][D][T] -> xT[t][b][d] ------------------------
__global__ __launch_bounds__(256) void transpose_x(const float* __restrict__ x) {
  __shared__ float tile[32][33];
  const int t0 = blockIdx.x * 32, d0 = blockIdx.y * 32, b = blockIdx.z;
  const int tx = threadIdx.x, ty = threadIdx.y;
  for (int i = ty; i < 32; i += 8)
    tile[i][tx] = x[((long)b * DIN + d0 + i) * T_LEN + t0 + tx];
  __syncthreads();
  for (int i = ty; i < 32; i += 8)
    g_xT[((long)(t0 + i) * BATCH + b) * DIN + d0 + tx] = tile[tx][i];
}

__global__ void init_bar() {
  if (threadIdx.x < 16) *(volatile unsigned*)&g_cnt16[threadIdx.x * 64] = 0u;
}

__global__ void dummy_k() {}

// ---------------- phase 2: persistent scan, fused input GEMM ----------------
// 128 blocks x 512 threads. Block owns units j = blk*4+{0..3}: 16 W_hh rows
// (stride 516) + 16 W_ih rows (stride 268, 16B-aligned) resident in SMEM.
// Warp wid: h k-range [wid*32,+32) (producers [wid*8,+8), counter wid,
// target 32t), x d-range [wid*16,+16). Lane = rg*8+bg; tile 4 rows x 4 b.
// Step: bar0 -> gx-part FMA (fills arrival window) -> poll -> stage h (8
// LDG.128+8 STS.128, SW-swizzled) -> h-part FMA -> spill -> bar1 ->
// reducers (tid<128): 16-partial sum + bias -> gates -> h store -> RED;
// others: stage next x tile (32KB from L2, single-buffered).
#define KW      516
#define KX      268
#define SM_W    (16 * KW)              // 8256
#define SM_WX   (16 * KX)              // 4288
#define SM_H    (16 * 1024)            // 16384
#define SM_XS   (16 * 512)             // 8192
#define SM_RED  (256 * 33)             // 8448
#define SMEM_SCAN_FLOATS (SM_W + SM_WX + SM_H + SM_XS + SM_RED + 32)
#define SMEM_SCAN_BYTES  (SMEM_SCAN_FLOATS * 4)

__global__ __launch_bounds__(NT, 1) void lstm_scan(
    const float* __restrict__ Whh, const float* __restrict__ Wih,
    const float* __restrict__ bih, const float* __restrict__ bhh) {
  extern __shared__ float sm[];
  float* Wsm  = sm;
  float* Wxsm = Wsm + SM_W;
  float* hsm  = Wxsm + SM_WX;
  float* xsm  = hsm + SM_H;
  float* red  = xsm + SM_XS;
  float* bias = red + SM_RED;

  const int tid = threadIdx.x, blk = blockIdx.x;
  const int wid = tid >> 5, lane = tid & 31;
  const int rg = lane >> 3, bg = lane & 7;

  // ---- prologue staging ----
  for (int idx = tid; idx < 16 * HID; idx += NT) {
    int r = idx >> 9, k = idx & 511;
    Wsm[r * KW + k] = Whh[(long)((r >> 2) * HID + blk * 4 + (r & 3)) * HID + k];
  }
  for (int idx = tid; idx < 16 * DIN; idx += NT) {
    int r = idx >> 8, d = idx & 255;
    Wxsm[r * KX + d] = Wih[(long)((r >> 2) * HID + blk * 4 + (r & 3)) * DIN + d];
  }
  if (tid < 16) {
    int row = (tid >> 2) * HID + blk * 4 + (tid & 3);
    bias[tid] = bih[row] + bhh[row];
  }
  for (int i = tid; i < SM_H; i += NT) hsm[i] = 0.f;
  // stage x tile for t=0 (all threads)
  {
    const float4* srcx = (const float4*)g_xT;
    for (int f = tid; f < 2048; f += NT) {
      int b = f >> 6, w = (f >> 2) & 15, dg = f & 3;
      int word = w * 512 + dg * 128 +
                 (((b * 4) ^ (((b >> 3) & 7) << 2)) ^ ((dg & 1) << 4));
      *(float4*)(xsm + word) = srcx[f];
    }
  }

  const float* wp0 = Wsm + (rg * 4 + 0) * KW + wid * 32;
  const float* wp1 = Wsm + (rg * 4 + 1) * KW + wid * 32;
  const float* wp2 = Wsm + (rg * 4 + 2) * KW + wid * 32;
  const float* wp3 = Wsm + (rg * 4 + 3) * KW + wid * 32;
  const float* xp0 = Wxsm + (rg * 4 + 0) * KX + wid * 16;
  const float* xp1 = Wxsm + (rg * 4 + 1) * KX + wid * 16;
  const float* xp2 = Wxsm + (rg * 4 + 2) * KX + wid * 16;
  const float* xp3 = Wxsm + (rg * 4 + 3) * KX + wid * 16;
  float* hreg = hsm + wid * 1024;
  float* xreg = xsm + wid * 512;
  int bxw[4];
#pragma unroll
  for (int j = 0; j < 4; j++) {
    int b = bg * 4 + j;
    bxw[j] = (b * 4) ^ (((b >> 3) & 7) << 2);
  }
  const int bxl = (lane * 4) ^ (((lane >> 3) & 7) << 2);
  const int rb_j = tid >> 5, rb_b = tid & 31;   // reducers (tid<128)
  float c_reg = 0.f;

  for (int t = 0; t < T_LEN; t++) {
    __syncthreads();                            // bar0: xs(t) ready, red free

    // ---- gx-part: 4 rows x 4 batches x 16 d (independent of h) ----
    unsigned long long acc[4][4];
#pragma unroll
    for (int m = 0; m < 4; m++)
#pragma unroll
      for (int j = 0; j < 4; j++) acc[m][j] = 0ull;
#pragma unroll
    for (int i = 0; i < 4; i++) {
      ulonglong2 w0 = *(const ulonglong2*)(xp0 + i * 4);
      ulonglong2 w1 = *(const ulonglong2*)(xp1 + i * 4);
      ulonglong2 w2 = *(const ulonglong2*)(xp2 + i * 4);
      ulonglong2 w3 = *(const ulonglong2*)(xp3 + i * 4);
      const int xm = (i & 1) << 4;
      ulonglong2 h0 = *(const ulonglong2*)(xreg + i * 128 + (bxw[0] ^ xm));
      ulonglong2 h1 = *(const ulonglong2*)(xreg + i * 128 + (bxw[1] ^ xm));
      ulonglong2 h2 = *(const ulonglong2*)(xreg + i * 128 + (bxw[2] ^ xm));
      ulonglong2 h3 = *(const ulonglong2*)(xreg + i * 128 + (bxw[3] ^ xm));
      fma2(acc[0][0], w0.x, h0.x); fma2(acc[0][0], w0.y, h0.y);
      fma2(acc[0][1], w0.x, h1.x); fma2(acc[0][1], w0.y, h1.y);
      fma2(acc[0][2], w0.x, h2.x); fma2(acc[0][2], w0.y, h2.y);
      fma2(acc[0][3], w0.x, h3.x); fma2(acc[0][3], w0.y, h3.y);
      fma2(acc[1][0], w1.x, h0.x); fma2(acc[1][0], w1.y, h0.y);
      fma2(acc[1][1], w1.x, h1.x); fma2(acc[1][1], w1.y, h1.y);
      fma2(acc[1][2], w1.x, h2.x); fma2(acc[1][2], w1.y, h2.y);
      fma2(acc[1][3], w1.x, h3.x); fma2(acc[1][3], w1.y, h3.y);
      fma2(acc[2][0], w2.x, h0.x); fma2(acc[2][0], w2.y, h0.y);
      fma2(acc[2][1], w2.x, h1.x); fma2(acc[2][1], w2.y, h1.y);
      fma2(acc[2][2], w2.x, h2.x); fma2(acc[2][2], w2.y, h2.y);
      fma2(acc[2][3], w2.x, h3.x); fma2(acc[2][3], w2.y, h3.y);
      fma2(acc[3][0], w3.x, h0.x); fma2(acc[3][0], w3.y, h0.y);
      fma2(acc[3][1], w3.x, h1.x); fma2(acc[3][1], w3.y, h1.y);
      fma2(acc[3][2], w3.x, h2.x); fma2(acc[3][2], w3.y, h2.y);
      fma2(acc[3][3], w3.x, h3.x); fma2(acc[3][3], w3.y, h3.y);
    }

    // ---- warp-private h staging (R11-proven) ----
    if (t > 0) {
      const unsigned tgt = 32u * (unsigned)t;
      unsigned v;
      do {
        asm volatile("ld.acquire.gpu.global.u32 %0, [%1];"
                     : "=r"(v) : "l"(&g_cnt16[wid * 64]) : "memory");
      } while (v < tgt);
      const float4* src = (const float4*)(g_hs4 + (long)(t - 1) * (NB * BATCH * 4))
                          + wid * 256;
      float4 s0 = src[0 * 32 + lane];
      float4 s1 = src[1 * 32 + lane];
      float4 s2 = src[2 * 32 + lane];
      float4 s3 = src[3 * 32 + lane];
      float4 s4 = src[4 * 32 + lane];
      float4 s5 = src[5 * 32 + lane];
      float4 s6 = src[6 * 32 + lane];
      float4 s7 = src[7 * 32 + lane];
      *(float4*)(hreg + 0 * 128 + (bxl ^ 0))  = s0;
      *(float4*)(hreg + 1 * 128 + (bxl ^ 16)) = s1;
      *(float4*)(hreg + 2 * 128 + (bxl ^ 0))  = s2;
      *(float4*)(hreg + 3 * 128 + (bxl ^ 16)) = s3;
      *(float4*)(hreg + 4 * 128 + (bxl ^ 0))  = s4;
      *(float4*)(hreg + 5 * 128 + (bxl ^ 16)) = s5;
      *(float4*)(hreg + 6 * 128 + (bxl ^ 0))  = s6;
      *(float4*)(hreg + 7 * 128 + (bxl ^ 16)) = s7;
      __syncwarp();
    }

    // ---- h-part: 4 rows x 4 batches x 32 k ----
#pragma unroll
    for (int i = 0; i < 8; i++) {
      ulonglong2 w0 = *(const ulonglong2*)(wp0 + i * 4);
      ulonglong2 w1 = *(const ulonglong2*)(wp1 + i * 4);
      ulonglong2 w2 = *(const ulonglong2*)(wp2 + i * 4);
      ulonglong2 w3 = *(const ulonglong2*)(wp3 + i * 4);
      const int xm = (i & 1) << 4;
      ulonglong2 h0 = *(const ulonglong2*)(hreg + i * 128 + (bxw[0] ^ xm));
      ulonglong2 h1 = *(const ulonglong2*)(hreg + i * 128 + (bxw[1] ^ xm));
      ulonglong2 h2 = *(const ulonglong2*)(hreg + i * 128 + (bxw[2] ^ xm));
      ulonglong2 h3 = *(const ulonglong2*)(hreg + i * 128 + (bxw[3] ^ xm));
      fma2(acc[0][0], w0.x, h0.x); fma2(acc[0][0], w0.y, h0.y);
      fma2(acc[0][1], w0.x, h1.x); fma2(acc[0][1], w0.y, h1.y);
      fma2(acc[0][2], w0.x, h2.x); fma2(acc[0][2], w0.y, h2.y);
      fma2(acc[0][3], w0.x, h3.x); fma2(acc[0][3], w0.y, h3.y);
      fma2(acc[1][0], w1.x, h0.x); fma2(acc[1][0], w1.y, h0.y);
      fma2(acc[1][1], w1.x, h1.x); fma2(acc[1][1], w1.y, h1.y);
      fma2(acc[1][2], w1.x, h2.x); fma2(acc[1][2], w1.y, h2.y);
      fma2(acc[1][3], w1.x, h3.x); fma2(acc[1][3], w1.y, h3.y);
      fma2(acc[2][0], w2.x, h0.x); fma2(acc[2][0], w2.y, h0.y);
      fma2(acc[2][1], w2.x, h1.x); fma2(acc[2][1], w2.y, h1.y);
      fma2(acc[2][2], w2.x, h2.x); fma2(acc[2][2], w2.y, h2.y);
      fma2(acc[2][3], w2.x, h3.x); fma2(acc[2][3], w2.y, h3.y);
      fma2(acc[3][0], w3.x, h0.x); fma2(acc[3][0], w3.y, h0.y);
      fma2(acc[3][1], w3.x, h1.x); fma2(acc[3][1], w3.y, h1.y);
      fma2(acc[3][2], w3.x, h2.x); fma2(acc[3][2], w3.y, h2.y);
      fma2(acc[3][3], w3.x, h3.x); fma2(acc[3][3], w3.y, h3.y);
    }

    // ---- spill: row = wid*16 + rg*4 + m, col = bg*4 + (j^rg) ----
#pragma unroll
    for (int m = 0; m < 4; m++) {
      float* rp = red + (wid * 16 + rg * 4 + m) * 33 + bg * 4;
#pragma unroll
      for (int j = 0; j < 4; j++) rp[j ^ rg] = hsum2(acc[m][j]);
    }
    __syncthreads();                            // bar1

    if (tid < 128) {
      // ---- reduce + gates ----
      float s0 = bias[0 * 4 + rb_j];
      float s1 = bias[1 * 4 + rb_j];
      float s2 = bias[2 * 4 + rb_j];
      float s3 = bias[3 * 4 + rb_j];
      const int c0 = (rb_b & ~3) | ((rb_b & 3) ^ 0);
      const int c1 = (rb_b & ~3) | ((rb_b & 3) ^ 1);
      const int c2 = (rb_b & ~3) | ((rb_b & 3) ^ 2);
      const int c3 = (rb_b & ~3) | ((rb_b & 3) ^ 3);
#pragma unroll
      for (int p = 0; p < 16; p++) {
        s0 += red[(p * 16 + 0 * 4 + rb_j) * 33 + c0];
        s1 += red[(p * 16 + 1 * 4 + rb_j) * 33 + c1];
        s2 += red[(p * 16 + 2 * 4 + rb_j) * 33 + c2];
        s3 += red[(p * 16 + 3 * 4 + rb_j) * 33 + c3];
      }
      float ig = fast_sig(s0);
      float fg = fast_sig(s1);
      float gg = fast_tanh(s2);
      float og = fast_sig(s3);
      c_reg = fg * c_reg + ig * gg;
      float h = og * fast_tanh(c_reg);
      g_hs4[((long)t * NB + blk) * (BATCH * 4) + rb_b * 4 + rb_j] = h;
      __syncwarp();
      if ((tid & 31) == 0)
        asm volatile("red.release.gpu.global.add.u32 [%0], %1;"
                     :: "l"(&g_cnt16[(blk >> 3) * 64]), "r"(1u) : "memory");
    } else if (t + 1 < T_LEN) {
      // ---- stage next x tile (tid 128..511) ----
      const float4* srcx = (const float4*)(g_xT + (long)(t + 1) * (BATCH * DIN));
      for (int f = tid - 128; f < 2048; f += 384) {
        int b = f >> 6, w = (f >> 2) & 15, dg = f & 3;
        int word = w * 512 + dg * 128 +
                   (((b * 4) ^ (((b >> 3) & 7) << 2)) ^ ((dg & 1) << 4));
        *(float4*)(xsm + word) = srcx[f];
      }
    }
  }
}

// ---------------- phase 3: hs4[T][k4][b][4] -> out[B][H][T] ---------------
__global__ __launch_bounds__(256) void transpose_hs(float* __restrict__ out) {
  __shared__ float tile[32][33];
  const int t0 = blockIdx.x * 32, j0 = blockIdx.y * 32, b = blockIdx.z;
  const int tx = threadIdx.x, ty = threadIdx.y;
  for (int i = ty; i < 32; i += 8) {
    int j = j0 + tx;
    tile[i][tx] = g_hs4[(((long)(t0 + i) * NB + (j >> 2)) * BATCH + b) * 4 + (j & 3)];
  }
  __syncthreads();
  for (int i = ty; i < 32; i += 8)
    out[((long)b * HID + j0 + i) * T_LEN + t0 + tx] = tile[tx][i];
}

// ---------------- launch ----------------
extern "C" void kernel_launch(void* const* d_in, const int* in_sizes, int n_in,
                              void* d_out, int out_size) {
  (void)in_sizes; (void)n_in; (void)out_size;
  const float* x   = (const float*)d_in[0];
  const float* Wih = (const float*)d_in[1];
  const float* Whh = (const float*)d_in[2];
  const float* bih = (const float*)d_in[3];
  const float* bhh = (const float*)d_in[4];
  float* out = (float*)d_out;

  cudaFuncSetAttribute(lstm_scan, cudaFuncAttributeMaxDynamicSharedMemorySize,
                       SMEM_SCAN_BYTES);

  dim3 gx(T_LEN / 32, DIN / 32, BATCH);
  transpose_x<<<gx, dim3(32, 8)>>>(x);                         // launch 1
  init_bar<<<1, 32>>>();                                        // launch 2
  dummy_k<<<1, 32>>>();                                         // launch 3
  lstm_scan<<<NB, NT, SMEM_SCAN_BYTES>>>(Whh, Wih, bih, bhh);   // launch 4
  dim3 g3(T_LEN / 32, HID / 32, BATCH);
  transpose_hs<<<g3, dim3(32, 8)>>>(out);                       // launch 5
}

// round 15
// speedup vs baseline: 1.0659x; 1.0659x over previous
#include <cuda_runtime.h>
#include <math.h>
#include <stdint.h>

#define T_LEN 1024
#define BATCH 32
#define DIN   256
#define HID   512
#define NB    128
#define NT    512

__device__ float g_xT[(long)T_LEN * BATCH * DIN];       // [t][b][d]  32MB
__device__ float g_hs4[(long)T_LEN * NB * BATCH * 4];   // [t][k4=blk][b][4j]
__device__ unsigned g_cnt16[1024];                      // 16 counters at w*64

// ---------------------------------------------------------------- helpers
__device__ __forceinline__ float fast_tanh(float x) {
  float y; asm("tanh.approx.f32 %0, %1;" : "=f"(y) : "f"(x)); return y;
}
__device__ __forceinline__ float fast_sig(float x) {
  return 0.5f * fast_tanh(0.5f * x) + 0.5f;
}
__device__ __forceinline__ void fma2(unsigned long long& d,
                                     unsigned long long a, unsigned long long b) {
  asm("fma.rn.f32x2 %0, %1, %2, %0;" : "+l"(d) : "l"(a), "l"(b));
}
__device__ __forceinline__ float hsum2(unsigned long long v) {
  return __uint_as_float((unsigned)v) + __uint_as_float((unsigned)(v >> 32));
}
__device__ __forceinline__ void cp_async16(void* smem_dst, const void* gsrc) {
  uint32_t s = (uint32_t)__cvta_generic_to_shared(smem_dst);
  asm volatile("cp.async.cg.shared.global [%0], [%1], 16;\n" :: "r"(s), "l"(gsrc));
}

// ---------------- phase 0: x[B][D][T] -> xT[t][b][d] ------------------------
__global__ __launch_bounds__(256) void transpose_x(const float* __restrict__ x) {
  __shared__ float tile[32][33];
  const int t0 = blockIdx.x * 32, d0 = blockIdx.y * 32, b = blockIdx.z;
  const int tx = threadIdx.x, ty = threadIdx.y;
  for (int i = ty; i < 32; i += 8)
    tile[i][tx] = x[((long)b * DIN + d0 + i) * T_LEN + t0 + tx];
  __syncthreads();
  for (int i = ty; i < 32; i += 8)
    g_xT[((long)(t0 + i) * BATCH + b) * DIN + d0 + tx] = tile[tx][i];
}

__global__ void init_bar() {
  if (threadIdx.x < 16) *(volatile unsigned*)&g_cnt16[threadIdx.x * 64] = 0u;
}

__global__ void dummy_k() {}

// ---------------- phase 2: persistent scan, fused input GEMM ----------------
// 128 blocks x 512 threads. Block owns units j = blk*4+{0..3}: 16 W_hh rows
// (stride 516) + 16 W_ih rows (stride 268) resident in SMEM. Warp wid:
// h k-range [wid*32,+32) (producers [wid*8,+8), counter wid, target 32t),
// x d-range [wid*16,+16) staged into warp-PRIVATE xsm region by the warp
// itself via cp.async (issued after its own gx-part reads; completion
// collected by wait_group 0 at next step's top -> full-step latency hiding).
// Step: bar0 -> wait_group -> gx-part FMA -> issue cp.async x(t+1) ->
// poll -> stage h (8 LDG.128 + 8 STS.128, SW-swizzled) -> h-part FMA ->
// spill -> bar1 -> reducers (tid<128): sum + bias -> gates -> h store -> RED.
#define KW      516
#define KX      268
#define SM_W    (16 * KW)              // 8256
#define SM_WX   (16 * KX)              // 4288
#define SM_H    (16 * 1024)            // 16384
#define SM_XS   (16 * 512)             // 8192
#define SM_RED  (256 * 33)             // 8448
#define SMEM_SCAN_FLOATS (SM_W + SM_WX + SM_H + SM_XS + SM_RED + 32)
#define SMEM_SCAN_BYTES  (SMEM_SCAN_FLOATS * 4)

__global__ __launch_bounds__(NT, 1) void lstm_scan(
    const float* __restrict__ Whh, const float* __restrict__ Wih,
    const float* __restrict__ bih, const float* __restrict__ bhh) {
  extern __shared__ float sm[];
  float* Wsm  = sm;
  float* Wxsm = Wsm + SM_W;
  float* hsm  = Wxsm + SM_WX;
  float* xsm  = hsm + SM_H;
  float* red  = xsm + SM_XS;
  float* bias = red + SM_RED;

  const int tid = threadIdx.x, blk = blockIdx.x;
  const int wid = tid >> 5, lane = tid & 31;
  const int rg = lane >> 3, bg = lane & 7;

  // ---- prologue staging ----
  for (int idx = tid; idx < 16 * HID; idx += NT) {
    int r = idx >> 9, k = idx & 511;
    Wsm[r * KW + k] = Whh[(long)((r >> 2) * HID + blk * 4 + (r & 3)) * HID + k];
  }
  for (int idx = tid; idx < 16 * DIN; idx += NT) {
    int r = idx >> 8, d = idx & 255;
    Wxsm[r * KX + d] = Wih[(long)((r >> 2) * HID + blk * 4 + (r & 3)) * DIN + d];
  }
  if (tid < 16) {
    int row = (tid >> 2) * HID + blk * 4 + (tid & 3);
    bias[tid] = bih[row] + bhh[row];
  }
  for (int i = tid; i < SM_H; i += NT) hsm[i] = 0.f;
  // stage x tile for t=0 (all threads, direct)
  {
    const float4* srcx = (const float4*)g_xT;
    for (int f = tid; f < 2048; f += NT) {
      int b = f >> 6, w = (f >> 2) & 15, dg = f & 3;
      int word = w * 512 + dg * 128 +
                 (((b * 4) ^ (((b >> 3) & 7) << 2)) ^ ((dg & 1) << 4));
      *(float4*)(xsm + word) = srcx[f];
    }
  }

  const float* wp0 = Wsm + (rg * 4 + 0) * KW + wid * 32;
  const float* wp1 = Wsm + (rg * 4 + 1) * KW + wid * 32;
  const float* wp2 = Wsm + (rg * 4 + 2) * KW + wid * 32;
  const float* wp3 = Wsm + (rg * 4 + 3) * KW + wid * 32;
  const float* xp0 = Wxsm + (rg * 4 + 0) * KX + wid * 16;
  const float* xp1 = Wxsm + (rg * 4 + 1) * KX + wid * 16;
  const float* xp2 = Wxsm + (rg * 4 + 2) * KX + wid * 16;
  const float* xp3 = Wxsm + (rg * 4 + 3) * KX + wid * 16;
  float* hreg = hsm + wid * 1024;
  float* xreg = xsm + wid * 512;
  int bxw[4];
#pragma unroll
  for (int j = 0; j < 4; j++) {
    int b = bg * 4 + j;
    bxw[j] = (b * 4) ^ (((b >> 3) & 7) << 2);
  }
  const int bxl = (lane * 4) ^ (((lane >> 3) & 7) << 2);
  // per-lane x staging map: dg = lane&3, batches lane>>2 + {0,8,16,24}
  const int x_dg = lane & 3, x_b0 = lane >> 2;
  int xw[4];
#pragma unroll
  for (int u = 0; u < 4; u++) {
    int b = x_b0 + u * 8;
    xw[u] = wid * 512 + x_dg * 128 +
            ((((b * 4) ^ (((b >> 3) & 7) << 2))) ^ ((x_dg & 1) << 4));
  }
  const int rb_j = tid >> 5, rb_b = tid & 31;   // reducers (tid<128)
  float c_reg = 0.f;

  for (int t = 0; t < T_LEN; t++) {
    __syncthreads();                            // bar0: red free
    asm volatile("cp.async.wait_group 0;\n" ::: "memory");  // x(t) landed

    // ---- gx-part: 4 rows x 4 batches x 16 d (independent of h) ----
    unsigned long long acc[4][4];
#pragma unroll
    for (int m = 0; m < 4; m++)
#pragma unroll
      for (int j = 0; j < 4; j++) acc[m][j] = 0ull;
#pragma unroll
    for (int i = 0; i < 4; i++) {
      ulonglong2 w0 = *(const ulonglong2*)(xp0 + i * 4);
      ulonglong2 w1 = *(const ulonglong2*)(xp1 + i * 4);
      ulonglong2 w2 = *(const ulonglong2*)(xp2 + i * 4);
      ulonglong2 w3 = *(const ulonglong2*)(xp3 + i * 4);
      const int xm = (i & 1) << 4;
      ulonglong2 h0 = *(const ulonglong2*)(xreg + i * 128 + (bxw[0] ^ xm));
      ulonglong2 h1 = *(const ulonglong2*)(xreg + i * 128 + (bxw[1] ^ xm));
      ulonglong2 h2 = *(const ulonglong2*)(xreg + i * 128 + (bxw[2] ^ xm));
      ulonglong2 h3 = *(const ulonglong2*)(xreg + i * 128 + (bxw[3] ^ xm));
      fma2(acc[0][0], w0.x, h0.x); fma2(acc[0][0], w0.y, h0.y);
      fma2(acc[0][1], w0.x, h1.x); fma2(acc[0][1], w0.y, h1.y);
      fma2(acc[0][2], w0.x, h2.x); fma2(acc[0][2], w0.y, h2.y);
      fma2(acc[0][3], w0.x, h3.x); fma2(acc[0][3], w0.y, h3.y);
      fma2(acc[1][0], w1.x, h0.x); fma2(acc[1][0], w1.y, h0.y);
      fma2(acc[1][1], w1.x, h1.x); fma2(acc[1][1], w1.y, h1.y);
      fma2(acc[1][2], w1.x, h2.x); fma2(acc[1][2], w1.y, h2.y);
      fma2(acc[1][3], w1.x, h3.x); fma2(acc[1][3], w1.y, h3.y);
      fma2(acc[2][0], w2.x, h0.x); fma2(acc[2][0], w2.y, h0.y);
      fma2(acc[2][1], w2.x, h1.x); fma2(acc[2][1], w2.y, h1.y);
      fma2(acc[2][2], w2.x, h2.x); fma2(acc[2][2], w2.y, h2.y);
      fma2(acc[2][3], w2.x, h3.x); fma2(acc[2][3], w2.y, h3.y);
      fma2(acc[3][0], w3.x, h0.x); fma2(acc[3][0], w3.y, h0.y);
      fma2(acc[3][1], w3.x, h1.x); fma2(acc[3][1], w3.y, h1.y);
      fma2(acc[3][2], w3.x, h2.x); fma2(acc[3][2], w3.y, h2.y);
      fma2(acc[3][3], w3.x, h3.x); fma2(acc[3][3], w3.y, h3.y);
    }

    // ---- issue x(t+1) staging: warp-private region, cp.async (no regs) ----
    if (t + 1 < T_LEN) {
      const float4* srcx = (const float4*)(g_xT + (long)(t + 1) * (BATCH * DIN));
#pragma unroll
      for (int u = 0; u < 4; u++) {
        int b = x_b0 + u * 8;
        cp_async16(xsm + xw[u], srcx + b * 64 + wid * 4 + x_dg);
      }
      asm volatile("cp.async.commit_group;\n");
    }

    // ---- warp-private h staging (R11-proven) ----
    if (t > 0) {
      const unsigned tgt = 32u * (unsigned)t;
      unsigned v;
      do {
        asm volatile("ld.acquire.gpu.global.u32 %0, [%1];"
                     : "=r"(v) : "l"(&g_cnt16[wid * 64]) : "memory");
      } while (v < tgt);
      const float4* src = (const float4*)(g_hs4 + (long)(t - 1) * (NB * BATCH * 4))
                          + wid * 256;
      float4 s0 = src[0 * 32 + lane];
      float4 s1 = src[1 * 32 + lane];
      float4 s2 = src[2 * 32 + lane];
      float4 s3 = src[3 * 32 + lane];
      float4 s4 = src[4 * 32 + lane];
      float4 s5 = src[5 * 32 + lane];
      float4 s6 = src[6 * 32 + lane];
      float4 s7 = src[7 * 32 + lane];
      *(float4*)(hreg + 0 * 128 + (bxl ^ 0))  = s0;
      *(float4*)(hreg + 1 * 128 + (bxl ^ 16)) = s1;
      *(float4*)(hreg + 2 * 128 + (bxl ^ 0))  = s2;
      *(float4*)(hreg + 3 * 128 + (bxl ^ 16)) = s3;
      *(float4*)(hreg + 4 * 128 + (bxl ^ 0))  = s4;
      *(float4*)(hreg + 5 * 128 + (bxl ^ 16)) = s5;
      *(float4*)(hreg + 6 * 128 + (bxl ^ 0))  = s6;
      *(float4*)(hreg + 7 * 128 + (bxl ^ 16)) = s7;
      __syncwarp();
    }

    // ---- h-part: 4 rows x 4 batches x 32 k ----
#pragma unroll
    for (int i = 0; i < 8; i++) {
      ulonglong2 w0 = *(const ulonglong2*)(wp0 + i * 4);
      ulonglong2 w1 = *(const ulonglong2*)(wp1 + i * 4);
      ulonglong2 w2 = *(const ulonglong2*)(wp2 + i * 4);
      ulonglong2 w3 = *(const ulonglong2*)(wp3 + i * 4);
      const int xm = (i & 1) << 4;
      ulonglong2 h0 = *(const ulonglong2*)(hreg + i * 128 + (bxw[0] ^ xm));
      ulonglong2 h1 = *(const ulonglong2*)(hreg + i * 128 + (bxw[1] ^ xm));
      ulonglong2 h2 = *(const ulonglong2*)(hreg + i * 128 + (bxw[2] ^ xm));
      ulonglong2 h3 = *(const ulonglong2*)(hreg + i * 128 + (bxw[3] ^ xm));
      fma2(acc[0][0], w0.x, h0.x); fma2(acc[0][0], w0.y, h0.y);
      fma2(acc[0][1], w0.x, h1.x); fma2(acc[0][1], w0.y, h1.y);
      fma2(acc[0][2], w0.x, h2.x); fma2(acc[0][2], w0.y, h2.y);
      fma2(acc[0][3], w0.x, h3.x); fma2(acc[0][3], w0.y, h3.y);
      fma2(acc[1][0], w1.x, h0.x); fma2(acc[1][0], w1.y, h0.y);
      fma2(acc[1][1], w1.x, h1.x); fma2(acc[1][1], w1.y, h1.y);
      fma2(acc[1][2], w1.x, h2.x); fma2(acc[1][2], w1.y, h2.y);
      fma2(acc[1][3], w1.x, h3.x); fma2(acc[1][3], w1.y, h3.y);
      fma2(acc[2][0], w2.x, h0.x); fma2(acc[2][0], w2.y, h0.y);
      fma2(acc[2][1], w2.x, h1.x); fma2(acc[2][1], w2.y, h1.y);
      fma2(acc[2][2], w2.x, h2.x); fma2(acc[2][2], w2.y, h2.y);
      fma2(acc[2][3], w2.x, h3.x); fma2(acc[2][3], w2.y, h3.y);
      fma2(acc[3][0], w3.x, h0.x); fma2(acc[3][0], w3.y, h0.y);
      fma2(acc[3][1], w3.x, h1.x); fma2(acc[3][1], w3.y, h1.y);
      fma2(acc[3][2], w3.x, h2.x); fma2(acc[3][2], w3.y, h2.y);
      fma2(acc[3][3], w3.x, h3.x); fma2(acc[3][3], w3.y, h3.y);
    }

    // ---- spill: row = wid*16 + rg*4 + m, col = bg*4 + (j^rg) ----
#pragma unroll
    for (int m = 0; m < 4; m++) {
      float* rp = red + (wid * 16 + rg * 4 + m) * 33 + bg * 4;
#pragma unroll
      for (int j = 0; j < 4; j++) rp[j ^ rg] = hsum2(acc[m][j]);
    }
    __syncthreads();                            // bar1

    if (tid < 128) {
      // ---- reduce + gates ----
      float s0 = bias[0 * 4 + rb_j];
      float s1 = bias[1 * 4 + rb_j];
      float s2 = bias[2 * 4 + rb_j];
      float s3 = bias[3 * 4 + rb_j];
      const int c0 = (rb_b & ~3) | ((rb_b & 3) ^ 0);
      const int c1 = (rb_b & ~3) | ((rb_b & 3) ^ 1);
      const int c2 = (rb_b & ~3) | ((rb_b & 3) ^ 2);
      const int c3 = (rb_b & ~3) | ((rb_b & 3) ^ 3);
#pragma unroll
      for (int p = 0; p < 16; p++) {
        s0 += red[(p * 16 + 0 * 4 + rb_j) * 33 + c0];
        s1 += red[(p * 16 + 1 * 4 + rb_j) * 33 + c1];
        s2 += red[(p * 16 + 2 * 4 + rb_j) * 33 + c2];
        s3 += red[(p * 16 + 3 * 4 + rb_j) * 33 + c3];
      }
      float ig = fast_sig(s0);
      float fg = fast_sig(s1);
      float gg = fast_tanh(s2);
      float og = fast_sig(s3);
      c_reg = fg * c_reg + ig * gg;
      float h = og * fast_tanh(c_reg);
      g_hs4[((long)t * NB + blk) * (BATCH * 4) + rb_b * 4 + rb_j] = h;
      __syncwarp();
      if ((tid & 31) == 0)
        asm volatile("red.release.gpu.global.add.u32 [%0], %1;"
                     :: "l"(&g_cnt16[(blk >> 3) * 64]), "r"(1u) : "memory");
    }
  }
}

// ---------------- phase 3: hs4[T][k4][b][4] -> out[B][H][T] ---------------
__global__ __launch_bounds__(256) void transpose_hs(float* __restrict__ out) {
  __shared__ float tile[32][33];
  const int t0 = blockIdx.x * 32, j0 = blockIdx.y * 32, b = blockIdx.z;
  const int tx = threadIdx.x, ty = threadIdx.y;
  for (int i = ty; i < 32; i += 8) {
    int j = j0 + tx;
    tile[i][tx] = g_hs4[(((long)(t0 + i) * NB + (j >> 2)) * BATCH + b) * 4 + (j & 3)];
  }
  __syncthreads();
  for (int i = ty; i < 32; i += 8)
    out[((long)b * HID + j0 + i) * T_LEN + t0 + tx] = tile[tx][i];
}

// ---------------- launch ----------------
extern "C" void kernel_launch(void* const* d_in, const int* in_sizes, int n_in,
                              void* d_out, int out_size) {
  (void)in_sizes; (void)n_in; (void)out_size;
  const float* x   = (const float*)d_in[0];
  const float* Wih = (const float*)d_in[1];
  const float* Whh = (const float*)d_in[2];
  const float* bih = (const float*)d_in[3];
  const float* bhh = (const float*)d_in[4];
  float* out = (float*)d_out;

  cudaFuncSetAttribute(lstm_scan, cudaFuncAttributeMaxDynamicSharedMemorySize,
                       SMEM_SCAN_BYTES);

  dim3 gx(T_LEN / 32, DIN / 32, BATCH);
  transpose_x<<<gx, dim3(32, 8)>>>(x);                         // launch 1
  init_bar<<<1, 32>>>();                                        // launch 2
  dummy_k<<<1, 32>>>();                                         // launch 3
  lstm_scan<<<NB, NT, SMEM_SCAN_BYTES>>>(Whh, Wih, bih, bhh);   // launch 4
  dim3 g3(T_LEN / 32, HID / 32, BATCH);
  transpose_hs<<<g3, dim3(32, 8)>>>(out);                       // launch 5
}

// round 16
// speedup vs baseline: 1.2844x; 1.2050x over previous
#include <cuda_runtime.h>
#include <math.h>
#include <stdint.h>

#define T_LEN 1024
#define BATCH 32
#define DIN   256
#define HID   512
#define NB    128
#define NT    512

__device__ float g_xT2[(long)T_LEN * 16 * 512];
__device__ float g_hs4[(long)T_LEN * NB * BATCH * 4];
__device__ unsigned g_cnt16[1024];

__device__ __forceinline__ float fast_tanh(float x) {
  float y; asm("tanh.approx.f32 %0, %1;" : "=f"(y) : "f"(x)); return y;
}
__device__ __forceinline__ float fast_sig(float x) {
  return 0.5f * fast_tanh(0.5f * x) + 0.5f;
}
__device__ __forceinline__ void fma2(unsigned long long& d,
                                     unsigned long long a, unsigned long long b) {
  asm("fma.rn.f32x2 %0, %1, %2, %0;" : "+l"(d) : "l"(a), "l"(b));
}
__device__ __forceinline__ float hsum2(unsigned long long v) {
  return __uint_as_float((unsigned)v) + __uint_as_float((unsigned)(v >> 32));
}
__device__ __forceinline__ int xword(int b, int dg) {
  return dg * 128 + (((b * 4) ^ (((b >> 3) & 7) << 2)) ^ ((dg & 1) << 4));
}

__global__ __launch_bounds__(256) void transpose_x(const float* __restrict__ x) {
  __shared__ float tile[32][33];
  const int t0 = blockIdx.x * 32, d0 = blockIdx.y * 32, b = blockIdx.z;
  const int tx = threadIdx.x, ty = threadIdx.y;
  for (int i = ty; i < 32; i += 8)
    tile[i][tx] = x[((long)b * DIN + d0 + i) * T_LEN + t0 + tx];
  __syncthreads();
  for (int i = ty; i < 32; i += 8) {
    int t = t0 + tx, d = d0 + i;
    int w = d >> 4, dg = (d >> 2) & 3, c = d & 3;
    g_xT2[((long)t * 16 + w) * 512 + xword(b, dg) + c] = tile[i][tx];
  }
}

__global__ void init_bar() {
  if (threadIdx.x < 16) *(volatile unsigned*)&g_cnt16[threadIdx.x * 64] = 0u;
}

__global__ void dummy_k() {}

#define KW      516
#define KX      268
#define SM_W    (16 * KW)
#define SM_WX   (16 * KX)
#define SM_H    (16 * 1024)
#define SM_XS   (16 * 512)
#define SM_RED  (256 * 33)
#define SM_BIAS 32
#define SMEM_SCAN_FLOATS (SM_W + SM_WX + SM_H + SM_XS + SM_RED + SM_BIAS + 40)
#define SMEM_SCAN_BYTES  (SMEM_SCAN_FLOATS * 4)

__global__ __launch_bounds__(NT, 1) void lstm_scan(
    const float* __restrict__ Whh, const float* __restrict__ Wih,
    const float* __restrict__ bih, const float* __restrict__ bhh) {
  extern __shared__ float sm[];
  float* Wsm  = sm;
  float* Wxsm = Wsm + SM_W;
  float* hsm  = Wxsm + SM_WX;
  float* xsm  = hsm + SM_H;
  float* red  = xsm + SM_XS;
  float* bias = red + SM_RED;
  unsigned long long* mbar = (unsigned long long*)(bias + SM_BIAS);

  const int tid = threadIdx.x, blk = blockIdx.x;
  const int wid = tid >> 5, lane = tid & 31;
  const int rg = lane >> 3, bg = lane & 7;
  const uint32_t mb_base = (uint32_t)__cvta_generic_to_shared(mbar);

  for (int idx = tid; idx < 16 * HID; idx += NT) {
    int r = idx >> 9, k = idx & 511;
    Wsm[r * KW + k] = Whh[(long)((r >> 2) * HID + blk * 4 + (r & 3)) * HID + k];
  }
  for (int idx = tid; idx < 16 * DIN; idx += NT) {
    int r = idx >> 8, d = idx & 255;
    Wxsm[r * KX + d] = Wih[(long)((r >> 2) * HID + blk * 4 + (r & 3)) * DIN + d];
  }
  if (tid < 16) {
    int row = (tid >> 2) * HID + blk * 4 + (tid & 3);
    bias[tid] = bih[row] + bhh[row];
  }
  for (int i = tid; i < SM_H; i += NT) hsm[i] = 0.f;
  {
    const float4* srcx = (const float4*)g_xT2;
    float4* dstx = (float4*)xsm;
    for (int f = tid; f < 2048; f += NT) dstx[f] = srcx[f];
  }
  if (tid < 16)
    asm volatile("mbarrier.init.shared.b64 [%0], 1;" :: "r"(mb_base + tid * 8));
  __syncthreads();

  const float* wp0 = Wsm + (rg * 4 + 0) * KW + wid * 32;
  const float* wp1 = Wsm + (rg * 4 + 1) * KW + wid * 32;
  const float* wp2 = Wsm + (rg * 4 + 2) * KW + wid * 32;
  const float* wp3 = Wsm + (rg * 4 + 3) * KW + wid * 32;
  const float* xp0 = Wxsm + (rg * 4 + 0) * KX + wid * 16;
  const float* xp1 = Wxsm + (rg * 4 + 1) * KX + wid * 16;
  const float* xp2 = Wxsm + (rg * 4 + 2) * KX + wid * 16;
  const float* xp3 = Wxsm + (rg * 4 + 3) * KX + wid * 16;
  float* hreg = hsm + wid * 1024;
  float* xreg = xsm + wid * 512;
  int bxw[4];
#pragma unroll
  for (int j = 0; j < 4; j++) {
    int b = bg * 4 + j;
    bxw[j] = (b * 4) ^ (((b >> 3) & 7) << 2);
  }
  const int bxl = (lane * 4) ^ (((lane >> 3) & 7) << 2);
  const int rb_j = tid >> 5, rb_b = tid & 31;
  float c_reg = 0.f;

  for (int t = 0; t < T_LEN; t++) {
    __syncthreads();

    if (t > 0) {
      uint32_t mb = mb_base + wid * 8;
      uint32_t done = 0;
      unsigned phase = (unsigned)((t - 1) & 1);
      while (!done) {
        asm volatile(
          "{\n\t.reg .pred p;\n\t"
          "mbarrier.try_wait.parity.shared.b64 p, [%1], %2, 10000000;\n\t"
          "selp.b32 %0, 1, 0, p;\n\t}"
          : "=r"(done) : "r"(mb), "r"(phase) : "memory");
      }
    }

    unsigned long long acc[4][4];
#pragma unroll
    for (int m = 0; m < 4; m++)
#pragma unroll
      for (int j = 0; j < 4; j++) acc[m][j] = 0ull;
#pragma unroll
    for (int i = 0; i < 4; i++) {
      ulonglong2 w0 = *(const ulonglong2*)(xp0 + i * 4);
      ulonglong2 w1 = *(const ulonglong2*)(xp1 + i * 4);
      ulonglong2 w2 = *(const ulonglong2*)(xp2 + i * 4);
      ulonglong2 w3 = *(const ulonglong2*)(xp3 + i * 4);
      const int xm = (i & 1) << 4;
      ulonglong2 h0 = *(const ulonglong2*)(xreg + i * 128 + (bxw[0] ^ xm));
      ulonglong2 h1 = *(const ulonglong2*)(xreg + i * 128 + (bxw[1] ^ xm));
      ulonglong2 h2 = *(const ulonglong2*)(xreg + i * 128 + (bxw[2] ^ xm));
      ulonglong2 h3 = *(const ulonglong2*)(xreg + i * 128 + (bxw[3] ^ xm));
      fma2(acc[0][0], w0.x, h0.x); fma2(acc[0][0], w0.y, h0.y);
      fma2(acc[0][1], w0.x, h1.x); fma2(acc[0][1], w0.y, h1.y);
      fma2(acc[0][2], w0.x, h2.x); fma2(acc[0][2], w0.y, h2.y);
      fma2(acc[0][3], w0.x, h3.x); fma2(acc[0][3], w0.y, h3.y);
      fma2(acc[1][0], w1.x, h0.x); fma2(acc[1][0], w1.y, h0.y);
      fma2(acc[1][1], w1.x, h1.x); fma2(acc[1][1], w1.y, h1.y);
      fma2(acc[1][2], w1.x, h2.x); fma2(acc[1][2], w1.y, h2.y);
      fma2(acc[1][3], w1.x, h3.x); fma2(acc[1][3], w1.y, h3.y);
      fma2(acc[2][0], w2.x, h0.x); fma2(acc[2][0], w2.y, h0.y);
      fma2(acc[2][1], w2.x, h1.x); fma2(acc[2][1], w2.y, h1.y);
      fma2(acc[2][2], w2.x, h2.x); fma2(acc[2][2], w2.y, h2.y);
      fma2(acc[2][3], w2.x, h3.x); fma2(acc[2][3], w2.y, h3.y);
      fma2(acc[3][0], w3.x, h0.x); fma2(acc[3][0], w3.y, h0.y);
      fma2(acc[3][1], w3.x, h1.x); fma2(acc[3][1], w3.y, h1.y);
      fma2(acc[3][2], w3.x, h2.x); fma2(acc[3][2], w3.y, h2.y);
      fma2(acc[3][3], w3.x, h3.x); fma2(acc[3][3], w3.y, h3.y);
    }

    __syncwarp();
    if (lane == 0 && t + 1 < T_LEN) {
      uint32_t mb = mb_base + wid * 8;
      asm volatile("mbarrier.arrive.expect_tx.shared.b64 _, [%0], %1;"
                   :: "r"(mb), "r"(2048u));
      const float* src = g_xT2 + ((long)(t + 1) * 16 + wid) * 512;
      uint32_t d32 = (uint32_t)__cvta_generic_to_shared(xreg);
      asm volatile(
        "cp.async.bulk.shared::cluster.global.mbarrier::complete_tx::bytes "
        "[%0], [%1], %2, [%3];"
        :: "r"(d32), "l"(src), "r"(2048u), "r"(mb) : "memory");
    }

    if (t > 0) {
      const unsigned tgt = 32u * (unsigned)t;
      unsigned v;
      do {
        asm volatile("ld.acquire.gpu.global.u32 %0, [%1];"
                     : "=r"(v) : "l"(&g_cnt16[wid * 64]) : "memory");
      } while (v < tgt);
      const float4* src = (const float4*)(g_hs4 + (long)(t - 1) * (NB * BATCH * 4))
                          + wid * 256;
      float4 s0 = src[0 * 32 + lane];
      float4 s1 = src[1 * 32 + lane];
      float4 s2 = src[2 * 32 + lane];
      float4 s3 = src[3 * 32 + lane];
      float4 s4 = src[4 * 32 + lane];
      float4 s5 = src[5 * 32 + lane];
      float4 s6 = src[6 * 32 + lane];
      float4 s7 = src[7 * 32 + lane];
      *(float4*)(hreg + 0 * 128 + (bxl ^ 0))  = s0;
      *(float4*)(hreg + 1 * 128 + (bxl ^ 16)) = s1;
      *(float4*)(hreg + 2 * 128 + (bxl ^ 0))  = s2;
      *(float4*)(hreg + 3 * 128 + (bxl ^ 16)) = s3;
      *(float4*)(hreg + 4 * 128 + (bxl ^ 0))  = s4;
      *(float4*)(hreg + 5 * 128 + (bxl ^ 16)) = s5;
      *(float4*)(hreg + 6 * 128 + (bxl ^ 0))  = s6;
      *(float4*)(hreg + 7 * 128 + (bxl ^ 16)) = s7;
      __syncwarp();
    }

#pragma unroll
    for (int i = 0; i < 8; i++) {
      ulonglong2 w0 = *(const ulonglong2*)(wp0 + i * 4);
      ulonglong2 w1 = *(const ulonglong2*)(wp1 + i * 4);
      ulonglong2 w2 = *(const ulonglong2*)(wp2 + i * 4);
      ulonglong2 w3 = *(const ulonglong2*)(wp3 + i * 4);
      const int xm = (i & 1) << 4;
      ulonglong2 h0 = *(const ulonglong2*)(hreg + i * 128 + (bxw[0] ^ xm));
      ulonglong2 h1 = *(const ulonglong2*)(hreg + i * 128 + (bxw[1] ^ xm));
      ulonglong2 h2 = *(const ulonglong2*)(hreg + i * 128 + (bxw[2] ^ xm));
      ulonglong2 h3 = *(const ulonglong2*)(hreg + i * 128 + (bxw[3] ^ xm));
      fma2(acc[0][0], w0.x, h0.x); fma2(acc[0][0], w0.y, h0.y);
      fma2(acc[0][1], w0.x, h1.x); fma2(acc[0][1], w0.y, h1.y);
      fma2(acc[0][2], w0.x, h2.x); fma2(acc[0][2], w0.y, h2.y);
      fma2(acc[0][3], w0.x, h3.x); fma2(acc[0][3], w0.y, h3.y);
      fma2(acc[1][0], w1.x, h0.x); fma2(acc[1][0], w1.y, h0.y);
      fma2(acc[1][1], w1.x, h1.x); fma2(acc[1][1], w1.y, h1.y);
      fma2(acc[1][2], w1.x, h2.x); fma2(acc[1][2], w1.y, h2.y);
      fma2(acc[1][3], w1.x, h3.x); fma2(acc[1][3], w1.y, h3.y);
      fma2(acc[2][0], w2.x, h0.x); fma2(acc[2][0], w2.y, h0.y);
      fma2(acc[2][1], w2.x, h1.x); fma2(acc[2][1], w2.y, h1.y);
      fma2(acc[2][2], w2.x, h2.x); fma2(acc[2][2], w2.y, h2.y);
      fma2(acc[2][3], w2.x, h3.x); fma2(acc[2][3], w2.y, h3.y);
      fma2(acc[3][0], w3.x, h0.x); fma2(acc[3][0], w3.y, h0.y);
      fma2(acc[3][1], w3.x, h1.x); fma2(acc[3][1], w3.y, h1.y);
      fma2(acc[3][2], w3.x, h2.x); fma2(acc[3][2], w3.y, h2.y);
      fma2(acc[3][3], w3.x, h3.x); fma2(acc[3][3], w3.y, h3.y);
    }

#pragma unroll
    for (int m = 0; m < 4; m++) {
      float* rp = red + (wid * 16 + rg * 4 + m) * 33 + bg * 4;
#pragma unroll
      for (int j = 0; j < 4; j++) rp[j ^ rg] = hsum2(acc[m][j]);
    }
    __syncthreads();

    if (tid < 128) {
      float s0 = bias[0 * 4 + rb_j];
      float s1 = bias[1 * 4 + rb_j];
      float s2 = bias[2 * 4 + rb_j];
      float s3 = bias[3 * 4 + rb_j];
      const int c0 = (rb_b & ~3) | ((rb_b & 3) ^ 0);
      const int c1 = (rb_b & ~3) | ((rb_b & 3) ^ 1);
      const int c2 = (rb_b & ~3) | ((rb_b & 3) ^ 2);
      const int c3 = (rb_b & ~3) | ((rb_b & 3) ^ 3);
#pragma unroll
      for (int p = 0; p < 16; p++) {
        s0 += red[(p * 16 + 0 * 4 + rb_j) * 33 + c0];
        s1 += red[(p * 16 + 1 * 4 + rb_j) * 33 + c1];
        s2 += red[(p * 16 + 2 * 4 + rb_j) * 33 + c2];
        s3 += red[(p * 16 + 3 * 4 + rb_j) * 33 + c3];
      }
      float ig = fast_sig(s0);
      float fg = fast_sig(s1);
      float gg = fast_tanh(s2);
      float og = fast_sig(s3);
      c_reg = fg * c_reg + ig * gg;
      float h = og * fast_tanh(c_reg);
      g_hs4[((long)t * NB + blk) * (BATCH * 4) + rb_b * 4 + rb_j] = h;
      __syncwarp();
      if ((tid & 31) == 0)
        asm volatile("red.release.gpu.global.add.u32 [%0], %1;"
                     :: "l"(&g_cnt16[(blk >> 3) * 64]), "r"(1u) : "memory");
    }
  }
}

__global__ __launch_bounds__(256) void transpose_hs(float* __restrict__ out) {
  __shared__ float tile[32][33];
  const int t0 = blockIdx.x * 32, j0 = blockIdx.y * 32, b = blockIdx.z;
  const int tx = threadIdx.x, ty = threadIdx.y;
  for (int i = ty; i < 32; i += 8) {
    int j = j0 + tx;
    tile[i][tx] = g_hs4[(((long)(t0 + i) * NB + (j >> 2)) * BATCH + b) * 4 + (j & 3)];
  }
  __syncthreads();
  for (int i = ty; i < 32; i += 8)
    out[((long)b * HID + j0 + i) * T_LEN + t0 + tx] = tile[tx][i];
}

extern "C" void kernel_launch(void* const* d_in, const int* in_sizes, int n_in,
                              void* d_out, int out_size) {
  (void)in_sizes; (void)n_in; (void)out_size;
  const float* x   = (const float*)d_in[0];
  const float* Wih = (const float*)d_in[1];
  const float* Whh = (const float*)d_in[2];
  const float* bih = (const float*)d_in[3];
  const float* bhh = (const float*)d_in[4];
  float* out = (float*)d_out;

  cudaFuncSetAttribute(lstm_scan, cudaFuncAttributeMaxDynamicSharedMemorySize,
                       SMEM_SCAN_BYTES);

  dim3 gx(T_LEN / 32, DIN / 32, BATCH);
  transpose_x<<<gx, dim3(32, 8)>>>(x);
  init_bar<<<1, 32>>>();
  dummy_k<<<1, 32>>>();
  lstm_scan<<<NB, NT, SMEM_SCAN_BYTES>>>(Whh, Wih, bih, bhh);
  dim3 g3(T_LEN / 32, HID / 32, BATCH);
  transpose_hs<<<g3, dim3(32, 8)>>>(out);
}